// round 10
// baseline (speedup 1.0000x reference)
#include <cuda_runtime.h>
#include <stdint.h>

typedef unsigned long long ull;

#define OF 28672
#define IF 8192

// table: 256 groups x 40 ull (34 duplicated x'' pairs + 4 duplicated negbias pairs + 2 pad)
__device__ __align__(16) float g_xs[256 * 80];
__device__ float g_sumred[32];

__device__ const signed char c_xoff[34] = {
    0,1,2,3,4,5,6,7,8,9,10,
    10,11,12,13,14,15,16,17,18,19,20,21,
    21,22,23,24,25,26,27,28,29,30,31};
__device__ const signed char c_e[34] = {
    -10,-13,-16,-19,-12,-15,-18,-10,-13,-16,-19,
    -8,-11,-14,-17,-20,-13,-16,-19,-11,-14,-17,-20,
    -9,-12,-15,-18,-11,-14,-17,-20,-12,-15,-18};

__device__ __forceinline__ float pw2(int e) {
    return __int_as_float((127 + e) << 23);   // exact power of two
}

// prep1: 32 blocks x 256 -> partial sums of x
__global__ void prep1_kernel(const float* __restrict__ x) {
    __shared__ float red[256];
    int t = threadIdx.x;
    red[t] = x[blockIdx.x * 256 + t];
    __syncthreads();
    #pragma unroll
    for (int off = 128; off > 0; off >>= 1) {
        if (t < off) red[t] += red[t + off];
        __syncthreads();
    }
    if (t == 0) g_sumred[blockIdx.x] = red[0];
}

// prep2: x'' table + per-group neg biases + out init (bias - zeros*sumx)
#define TBL_N   (256 * 34)
#define NB_N    (256 * 4)
#define OUT_OFF (TBL_N + NB_N)
__global__ void prep2_kernel(const float* __restrict__ x,
                             const float* __restrict__ zeros,
                             const float* __restrict__ bias,
                             float* __restrict__ out) {
    __shared__ float s_sumx;
    if (threadIdx.x == 0) {
        float s = 0.f;
        #pragma unroll
        for (int k = 0; k < 32; k++) s += g_sumred[k];
        s_sumx = s;
    }
    __syncthreads();
    int e = blockIdx.x * 256 + threadIdx.x;
    if (e < TBL_N) {
        int g = e / 34, j = e % 34;
        float v = x[g * 32 + c_xoff[j]] * pw2(c_e[j]);
        g_xs[g * 80 + 2 * j]     = v;
        g_xs[g * 80 + 2 * j + 1] = v;
    } else if (e < OUT_OFF) {
        int i = e - TBL_N;
        int g = i >> 2, a = i & 3;
        double s = 0.0;
        for (int j = a; j < 34; j += 4)
            s += (double)(x[g * 32 + c_xoff[j]] * pw2(c_e[j]));
        float nb = (float)(s * -8388608.0);   // -2^23 * sum
        g_xs[g * 80 + 68 + 2 * a]     = nb;
        g_xs[g * 80 + 68 + 2 * a + 1] = nb;
    } else if (e < OUT_OFF + OF) {
        int i = e - OUT_OFF;
        out[i] = fmaf(-zeros[i], s_sumx, bias[i]);
    }
}

#define MAGIC64 0x4B0000004B000000ull
#define M64(m)  ((ull)(m) * 0x100000001ull)

#define FMA2(ACC, A, B) asm("fma.rn.f32x2 %0, %1, %2, %0;" : "+l"(ACC) : "l"(A), "l"(B))
#define ADD2(ACC, B)    asm("add.rn.f32x2 %0, %0, %1;"     : "+l"(ACC) : "l"(B))

// GEMV: grid (448, 4), 256 thr. Thread = 2 adjacent columns x 8 K-slices.
// 64-bit masked-magic datapath, one FFMA2 per 3-bit field, chunked x loads.
__global__ void __launch_bounds__(256) gemv3_kernel(
    const uint32_t* __restrict__ qw,
    const float* __restrict__ scales,
    float* __restrict__ out)
{
    __shared__ __align__(16) ull smx[2560];   // 64 groups x 40 ull
    __shared__ ull part[256];
    const int t = threadIdx.x;
    const int q = blockIdx.y;

    {
        const ulonglong2* src = (const ulonglong2*)g_xs + q * 1280;
        ulonglong2* dst = (ulonglong2*)smx;
        #pragma unroll
        for (int i = 0; i < 5; i++) dst[t + 256 * i] = src[t + 256 * i];
    }
    __syncthreads();

    const int lane = t & 31;
    const int sl   = t >> 5;
    const ull* p = (const ull*)(qw + (size_t)(3 * (q * 64 + sl * 8)) * OF
                                   + blockIdx.x * 64) + lane;
    const ull* xs = smx + (sl * 8) * 40;

    ull acc[4] = {0ull, 0ull, 0ull, 0ull};

    ull w0 = p[0], w1 = p[OF / 2], w2 = p[OF];

    #pragma unroll 1
    for (int g = 0; g < 8; g++) {
        p += 3 * (OF / 2);
        ull n0 = 0, n1 = 0, n2 = 0;
        if (g < 7) { n0 = p[0]; n1 = p[OF / 2]; n2 = p[OF]; }

        const ulonglong2* xq2 = (const ulonglong2*)xs;
        ulonglong2 xq;
        ull v;
        #define F(J, M, X) { ull mm = (v & M64(M)) | MAGIC64; FMA2(acc[(J) & 3], mm, X); }
        v = w0 << 10;
        xq = xq2[0];  F(0, 7u << 10, xq.x);  F(1, 7u << 13, xq.y);
        xq = xq2[1];  F(2, 7u << 16, xq.x);  F(3, 7u << 19, xq.y);
        v = w0;
        xq = xq2[2];  F(4, 7u << 12, xq.x);  F(5, 7u << 15, xq.y);
        xq = xq2[3];  F(6, 7u << 18, xq.x);
        v = w0 >> 11;                        F(7, 7u << 10, xq.y);
        xq = xq2[4];  F(8, 7u << 13, xq.x);  F(9, 7u << 16, xq.y);
        xq = xq2[5];  F(10, 3u << 19, xq.x);
        v = w1 << 10;                        F(11, 1u << 10, xq.y);
        xq = xq2[6];  F(12, 7u << 11, xq.x); F(13, 7u << 14, xq.y);
        xq = xq2[7];  F(14, 7u << 17, xq.x); F(15, 7u << 20, xq.y);
        v = w1;
        xq = xq2[8];  F(16, 7u << 13, xq.x); F(17, 7u << 16, xq.y);
        xq = xq2[9];  F(18, 7u << 19, xq.x);
        v = w1 >> 11;                        F(19, 7u << 11, xq.y);
        xq = xq2[10]; F(20, 7u << 14, xq.x); F(21, 7u << 17, xq.y);
        xq = xq2[11]; F(22, 1u << 20, xq.x);
        v = w2 << 10;                        F(23, 3u << 10, xq.y);
        xq = xq2[12]; F(24, 7u << 12, xq.x); F(25, 7u << 15, xq.y);
        xq = xq2[13]; F(26, 7u << 18, xq.x);
        v = w2;                              F(27, 7u << 11, xq.y);
        xq = xq2[14]; F(28, 7u << 14, xq.x); F(29, 7u << 17, xq.y);
        xq = xq2[15]; F(30, 7u << 20, xq.x);
        v = w2 >> 11;                        F(31, 7u << 12, xq.y);
        xq = xq2[16]; F(32, 7u << 15, xq.x); F(33, 7u << 18, xq.y);
        #undef F
        xq = xq2[17]; ADD2(acc[0], xq.x); ADD2(acc[1], xq.y);
        xq = xq2[18]; ADD2(acc[2], xq.x); ADD2(acc[3], xq.y);

        xs += 40;
        w0 = n0; w1 = n1; w2 = n2;
    }

    ADD2(acc[0], acc[1]);
    ADD2(acc[2], acc[3]);
    ADD2(acc[0], acc[2]);
    part[t] = acc[0];
    __syncthreads();

    if (t < 64) {
        const float* pf = (const float*)part;
        float dot = 0.f;
        #pragma unroll
        for (int s = 0; s < 8; s++)
            dot += pf[(s * 32 + (t >> 1)) * 2 + (t & 1)];
        const int c = blockIdx.x * 64 + t;
        atomicAdd(out + c, scales[c] * dot);
    }
}

extern "C" void kernel_launch(void* const* d_in, const int* in_sizes, int n_in,
                              void* d_out, int out_size) {
    const float*    x      = (const float*)d_in[0];
    const uint32_t* qw     = (const uint32_t*)d_in[1];
    const float*    scales = (const float*)d_in[2];
    const float*    zeros  = (const float*)d_in[3];
    const float*    bias   = (const float*)d_in[4];
    float*          out    = (float*)d_out;

    prep1_kernel<<<32, 256>>>(x);
    prep2_kernel<<<(OUT_OFF + OF + 255) / 256, 256>>>(x, zeros, bias, out);
    gemv3_kernel<<<dim3(OF / 64, 4), 256>>>(qw, scales, out);
}